// round 1
// baseline (speedup 1.0000x reference)
#include <cuda_runtime.h>
#include <math.h>

#define N_PIX  131072
#define DIM    720
#define NCLS   19
#define NPROTO 10
#define NJ     190
#define NJP    192
#define HWSZ   32768

// ---------------- scratch (device globals; no allocation allowed) -------------
__device__ float        g_cnorm[(size_t)N_PIX * DIM];   // 377 MB normalized features
__device__ float        g_stats[N_PIX * 4];             // mu, rstd, invL2
__device__ float        g_protosN[NJP * DIM];           // l2-normalized prototypes (padded)
__device__ float        g_E[N_PIX * NPROTO];            // exp(S/eps) for own class
__device__ float        g_bscale[N_PIX];                // sinkhorn column scales
__device__ double       g_S1[NJP];                      // sinkhorn row sums
__device__ int          g_cnt[NCLS];                    // class pixel counts
__device__ int          g_ncnt[NJP];                    // per (k,m) counts
__device__ int          g_picked[N_PIX];                // argmax prototype per pixel
__device__ unsigned char g_correct[N_PIX];
__device__ float        g_f[NJP * DIM];                 // prototype feature accum

// ---------------- utils -------------------------------------------------------
__device__ __forceinline__ float blockSum(float v, float* sh) {
    int lane = threadIdx.x & 31, w = threadIdx.x >> 5;
#pragma unroll
    for (int o = 16; o > 0; o >>= 1) v += __shfl_down_sync(0xffffffffu, v, o);
    __syncthreads();
    if (lane == 0) sh[w] = v;
    __syncthreads();
    if (w == 0) {
        v = (lane < 8) ? sh[lane] : 0.f;
#pragma unroll
        for (int o = 4; o > 0; o >>= 1) v += __shfl_down_sync(0xffffffffu, v, o);
        if (lane == 0) sh[0] = v;
    }
    __syncthreads();
    return sh[0];
}

// ---------------- zero scratch ------------------------------------------------
__global__ void k_zero() {
    int i = blockIdx.x * blockDim.x + threadIdx.x;
    if (i < NJP * DIM) g_f[i] = 0.f;
    if (i < NJP) g_ncnt[i] = 0;
    if (i < NCLS) g_cnt[i] = 0;
}

// ---------------- normalize prototypes ---------------------------------------
__global__ void k_protos(const float* __restrict__ pr) {
    __shared__ float sh[32];
    int j = blockIdx.x;           // 0..191 (190,191 padded with zeros)
    int tid = threadIdx.x;
    float v[3]; float ss = 0.f;
#pragma unroll
    for (int i = 0; i < 3; i++) {
        int d = tid + i * 256;
        float x = 0.f;
        if (j < NJ && d < DIM) x = pr[j * DIM + d];
        v[i] = x; ss += x * x;
    }
    float tot = blockSum(ss, sh);
    float inv = 1.f / fmaxf(sqrtf(tot), 1e-12f);
#pragma unroll
    for (int i = 0; i < 3; i++) {
        int d = tid + i * 256;
        if (d < DIM) g_protosN[j * DIM + d] = (j < NJ) ? v[i] * inv : 0.f;
    }
}

// ---------------- per-pixel LN+L2 stats (single pass over c) ------------------
__global__ void k_stats(const float* __restrict__ c,
                        const float* __restrict__ fg, const float* __restrict__ fb) {
    int n = blockIdx.x * blockDim.x + threadIdx.x;
    if (n >= N_PIX) return;
    int b = n >> 15, hw = n & (HWSZ - 1);
    const float* base = c + (size_t)b * DIM * HWSZ + hw;
    float s1 = 0, s2 = 0, sg2x2 = 0, sg2x = 0, sgbx = 0, sg2 = 0, sgb = 0, sb2 = 0;
#pragma unroll 4
    for (int d = 0; d < DIM; d++) {
        float x = base[(size_t)d * HWSZ];
        float g = fg[d], bb = fb[d];
        s1 += x; s2 += x * x;
        float gx = g * x;
        sg2x2 += gx * gx; sg2x += g * gx; sgbx += bb * gx;
        sg2 += g * g; sgb += g * bb; sb2 += bb * bb;
    }
    float mu  = s1 * (1.f / DIM);
    float var = s2 * (1.f / DIM) - mu * mu;
    float r   = rsqrtf(var + 1e-5f);
    // ||LN(x)*g + b||^2 closed form
    float ny2 = r * r * (sg2x2 - 2.f * mu * sg2x + mu * mu * sg2)
              + 2.f * r * (sgbx - mu * sgb) + sb2;
    float invL2 = 1.f / fmaxf(sqrtf(fmaxf(ny2, 0.f)), 1e-12f);
    g_stats[n * 4 + 0] = mu;
    g_stats[n * 4 + 1] = r;
    g_stats[n * 4 + 2] = invL2;
}

// ---------------- write normalized features (tiled transpose) -----------------
__global__ void k_writec(const float* __restrict__ c,
                         const float* __restrict__ fg, const float* __restrict__ fb) {
    __shared__ float t[48][33];
    int d0 = blockIdx.x * 48;          // 15 tiles cover 720
    int n0 = blockIdx.y * 32;          // 4096 tiles cover N
    int b = n0 >> 15, hw0 = n0 & (HWSZ - 1);
    int tid = threadIdx.x;
    for (int i = tid; i < 48 * 32; i += 256) {
        int dd = i >> 5, p = i & 31;
        t[dd][p] = c[((size_t)b * DIM + d0 + dd) * HWSZ + hw0 + p];
    }
    __syncthreads();
    for (int i = tid; i < 32 * 48; i += 256) {
        int p = i / 48, dd = i % 48;
        int n = n0 + p, d = d0 + dd;
        float mu = g_stats[n * 4], r = g_stats[n * 4 + 1], iL = g_stats[n * 4 + 2];
        float x = t[dd][p];
        g_cnorm[(size_t)n * DIM + d] = ((x - mu) * r * fg[d] + fb[d]) * iL;
    }
}

// ---------------- GEMM (128x192 full-J tile) + fused epilogue -----------------
#define GBM 128
#define GBK 16
#define SA_PITCH 132
#define SB_PITCH 196
#define SS_PITCH 193

__global__ __launch_bounds__(256, 1) void k_gemm(
    const int* __restrict__ gt, const float* __restrict__ mg, const float* __restrict__ mb,
    float* __restrict__ o_seg, float* __restrict__ o_pl)
{
    extern __shared__ float sm[];
    float* sA = sm;                          // [2][16][132]
    float* sB = sm + 2 * GBK * SA_PITCH;     // [2][16][196]
    const int tid = threadIdx.x;
    const int n0 = blockIdx.x * GBM;
    const int tx = tid & 15, ty = tid >> 4;

    const float* Ab = g_cnorm + (size_t)n0 * DIM;
    const int ar0 = tid >> 2;                // 0..63 (second row = +64)
    const int adq = (tid & 3) * 4;           // d sub-offset
    const int j0 = tid >> 2, j1 = (tid + 256) >> 2, j2 = (tid + 512) >> 2;

    float4 ra0, ra1, rb0, rb1, rb2;

#define LOAD_TILE(D0) do {                                                          \
    ra0 = *reinterpret_cast<const float4*>(Ab + (size_t)ar0 * DIM + (D0) + adq);    \
    ra1 = *reinterpret_cast<const float4*>(Ab + (size_t)(ar0 + 64) * DIM + (D0) + adq); \
    rb0 = *reinterpret_cast<const float4*>(g_protosN + (size_t)j0 * DIM + (D0) + adq);  \
    rb1 = *reinterpret_cast<const float4*>(g_protosN + (size_t)j1 * DIM + (D0) + adq);  \
    rb2 = *reinterpret_cast<const float4*>(g_protosN + (size_t)j2 * DIM + (D0) + adq);  \
} while (0)

#define STORE_TILE(BUF) do {                                                        \
    float* A_ = sA + (BUF) * GBK * SA_PITCH;                                        \
    float* B_ = sB + (BUF) * GBK * SB_PITCH;                                        \
    A_[(adq + 0) * SA_PITCH + ar0] = ra0.x;  A_[(adq + 1) * SA_PITCH + ar0] = ra0.y;\
    A_[(adq + 2) * SA_PITCH + ar0] = ra0.z;  A_[(adq + 3) * SA_PITCH + ar0] = ra0.w;\
    A_[(adq + 0) * SA_PITCH + ar0 + 64] = ra1.x; A_[(adq + 1) * SA_PITCH + ar0 + 64] = ra1.y; \
    A_[(adq + 2) * SA_PITCH + ar0 + 64] = ra1.z; A_[(adq + 3) * SA_PITCH + ar0 + 64] = ra1.w; \
    B_[(adq + 0) * SB_PITCH + j0] = rb0.x;   B_[(adq + 1) * SB_PITCH + j0] = rb0.y; \
    B_[(adq + 2) * SB_PITCH + j0] = rb0.z;   B_[(adq + 3) * SB_PITCH + j0] = rb0.w; \
    B_[(adq + 0) * SB_PITCH + j1] = rb1.x;   B_[(adq + 1) * SB_PITCH + j1] = rb1.y; \
    B_[(adq + 2) * SB_PITCH + j1] = rb1.z;   B_[(adq + 3) * SB_PITCH + j1] = rb1.w; \
    B_[(adq + 0) * SB_PITCH + j2] = rb2.x;   B_[(adq + 1) * SB_PITCH + j2] = rb2.y; \
    B_[(adq + 2) * SB_PITCH + j2] = rb2.z;   B_[(adq + 3) * SB_PITCH + j2] = rb2.w; \
} while (0)

    float acc[8][12];
#pragma unroll
    for (int i = 0; i < 8; i++)
#pragma unroll
        for (int j = 0; j < 12; j++) acc[i][j] = 0.f;

    LOAD_TILE(0);
    STORE_TILE(0);
    __syncthreads();

#pragma unroll 1
    for (int t = 0; t < 45; t++) {
        int cur = t & 1;
        if (t < 44) LOAD_TILE((t + 1) * GBK);
        const float* A_ = sA + cur * GBK * SA_PITCH;
        const float* B_ = sB + cur * GBK * SB_PITCH;
#pragma unroll
        for (int kk = 0; kk < GBK; kk++) {
            float4 a0 = *reinterpret_cast<const float4*>(A_ + kk * SA_PITCH + ty * 8);
            float4 a1 = *reinterpret_cast<const float4*>(A_ + kk * SA_PITCH + ty * 8 + 4);
            float4 b0 = *reinterpret_cast<const float4*>(B_ + kk * SB_PITCH + tx * 12);
            float4 b1 = *reinterpret_cast<const float4*>(B_ + kk * SB_PITCH + tx * 12 + 4);
            float4 b2 = *reinterpret_cast<const float4*>(B_ + kk * SB_PITCH + tx * 12 + 8);
            float av[8]  = {a0.x, a0.y, a0.z, a0.w, a1.x, a1.y, a1.z, a1.w};
            float bv[12] = {b0.x, b0.y, b0.z, b0.w, b1.x, b1.y, b1.z, b1.w, b2.x, b2.y, b2.z, b2.w};
#pragma unroll
            for (int i = 0; i < 8; i++)
#pragma unroll
                for (int j = 0; j < 12; j++)
                    acc[i][j] = fmaf(av[i], bv[j], acc[i][j]);
        }
        if (t < 44) { STORE_TILE(cur ^ 1); __syncthreads(); }
    }
    __syncthreads();

    // ---- stage results to smem (pitch 193, conflict-free column access) ----
    float* Ssh = sm;
#pragma unroll
    for (int i = 0; i < 8; i++)
#pragma unroll
        for (int j = 0; j < 12; j++)
            Ssh[(ty * 8 + i) * SS_PITCH + tx * 12 + j] = acc[i][j];
    int* shcnt = (int*)(sm + 128 * SS_PITCH);
    if (tid < NCLS) shcnt[tid] = 0;
    __syncthreads();

    // proto_logits
    for (int i = tid; i < 128 * NJ; i += 256) {
        int p = i / NJ, j = i % NJ;
        o_pl[(size_t)(n0 + p) * NJ + j] = Ssh[p * SS_PITCH + j];
    }

    // per-pixel epilogue
    if (tid < 128) {
        int p = tid, n = n0 + p;
        int kg = gt[n];
        float mk[NCLS];
        float mean = 0.f;
#pragma unroll
        for (int k = 0; k < NCLS; k++) {
            float mx = Ssh[p * SS_PITCH + k * NPROTO];
#pragma unroll
            for (int m = 1; m < NPROTO; m++)
                mx = fmaxf(mx, Ssh[p * SS_PITCH + k * NPROTO + m]);
            mk[k] = mx; mean += mx;
        }
        mean *= (1.f / NCLS);
        float var = 0.f;
#pragma unroll
        for (int k = 0; k < NCLS; k++) { float d = mk[k] - mean; var += d * d; }
        var *= (1.f / NCLS);
        float rs = rsqrtf(var + 1e-5f);
        int bI = n >> 15, hw = n & (HWSZ - 1);
        float best = -1e30f; int pred = 0;
#pragma unroll
        for (int k = 0; k < NCLS; k++) {
            float ln = (mk[k] - mean) * rs * mg[k] + mb[k];
            o_seg[((size_t)bI * NCLS + k) * HWSZ + hw] = ln;
            if (ln > best) { best = ln; pred = k; }
        }
        g_correct[n] = (pred == kg) ? 1 : 0;
#pragma unroll
        for (int m = 0; m < NPROTO; m++)
            g_E[n * NPROTO + m] = expf(Ssh[p * SS_PITCH + kg * NPROTO + m] * 20.f);
        atomicAdd(&shcnt[kg], 1);
    }
    __syncthreads();
    if (tid < NCLS && shcnt[tid]) atomicAdd(&g_cnt[tid], shcnt[tid]);
}

// ---------------- sinkhorn ----------------------------------------------------
__global__ void k_zeroS1() { if (threadIdx.x < NJP) g_S1[threadIdx.x] = 0.0; }

__global__ void k_sinkA(const int* __restrict__ gt, int useB) {
    __shared__ double sbin[NJP];
    int tid = threadIdx.x;
    for (int i = tid; i < NJP; i += 256) sbin[i] = 0.0;
    __syncthreads();
    for (int n = blockIdx.x * 256 + tid; n < N_PIX; n += gridDim.x * 256) {
        int k = gt[n];
        float bn = useB ? g_bscale[n] : 1.f;
        if (bn != 0.f) {
            double bd = (double)bn;
#pragma unroll
            for (int m = 0; m < NPROTO; m++)
                atomicAdd(&sbin[k * NPROTO + m], bd * (double)g_E[n * NPROTO + m]);
        }
    }
    __syncthreads();
    for (int i = tid; i < NJ; i += 256)
        if (sbin[i] != 0.0) atomicAdd(&g_S1[i], sbin[i]);
}

__global__ void k_sinkB(const int* __restrict__ gt, int final_it, float* __restrict__ o_pt) {
    int n = blockIdx.x * blockDim.x + threadIdx.x;
    if (n >= N_PIX) return;
    int k = gt[n];
    double a[NPROTO];
#pragma unroll
    for (int m = 0; m < NPROTO; m++) {
        double s = g_S1[k * NPROTO + m];
        a[m] = (s > 0.0) ? 1.0 / (10.0 * s) : 0.0;
    }
    float E[NPROTO];
#pragma unroll
    for (int m = 0; m < NPROTO; m++) E[m] = g_E[n * NPROTO + m];
    if (!final_it) {
        double t = 0.0;
#pragma unroll
        for (int m = 0; m < NPROTO; m++) t += a[m] * (double)E[m];
        int Bk = max(g_cnt[k], 1);
        g_bscale[n] = (t > 0.0) ? (float)(1.0 / ((double)Bk * t)) : 0.f;
    } else {
        double best = -1.0; int pm = 0;
#pragma unroll
        for (int m = 0; m < NPROTO; m++) {
            double v = a[m] * (double)E[m];
            if (v > best) { best = v; pm = m; }
        }
        g_picked[n] = pm;
        o_pt[n] = (float)(pm + NPROTO * k);
        if (g_correct[n]) atomicAdd(&g_ncnt[k * NPROTO + pm], 1);
    }
}

// ---------------- prototype feature scatter -----------------------------------
__global__ void k_scatter(const int* __restrict__ gt) {
    int warpId = (blockIdx.x * blockDim.x + threadIdx.x) >> 5;
    int lane = threadIdx.x & 31;
    int nwarps = (gridDim.x * blockDim.x) >> 5;
    for (int n = warpId; n < N_PIX; n += nwarps) {
        if (!g_correct[n]) continue;
        int row = gt[n] * NPROTO + g_picked[n];
        float* frow = g_f + (size_t)row * DIM;
        const float* crow = g_cnorm + (size_t)n * DIM;
        for (int d = lane; d < DIM; d += 32)
            atomicAdd(&frow[d], crow[d]);
    }
}

// ---------------- prototype EMA update ----------------------------------------
__global__ void k_update(float* __restrict__ o_pn) {
    __shared__ float sh[32];
    int r = blockIdx.x;            // 0..189
    int tid = threadIdx.x;
    float v[3], p[3];
    float ss = 0.f;
#pragma unroll
    for (int i = 0; i < 3; i++) {
        int d = tid + i * 256;
        bool ok = d < DIM;
        float x = ok ? g_f[(size_t)r * DIM + d] : 0.f;
        v[i] = x; ss += x * x;
        p[i] = ok ? g_protosN[(size_t)r * DIM + d] : 0.f;
    }
    float tot = blockSum(ss, sh);
    float invf = 1.f / fmaxf(sqrtf(tot), 1e-12f);
    bool upd = g_ncnt[r] > 0;
    float s2 = 0.f;
#pragma unroll
    for (int i = 0; i < 3; i++) {
        float val = upd ? (0.999f * p[i] + (1.0f - 0.999f) * v[i] * invf) : p[i];
        v[i] = val; s2 += val * val;
    }
    float tot2 = blockSum(s2, sh);
    float inv2 = 1.f / fmaxf(sqrtf(tot2), 1e-12f);
#pragma unroll
    for (int i = 0; i < 3; i++) {
        int d = tid + i * 256;
        if (d < DIM) o_pn[(size_t)r * DIM + d] = v[i] * inv2;
    }
}

// ---------------- launch ------------------------------------------------------
extern "C" void kernel_launch(void* const* d_in, const int* in_sizes, int n_in,
                              void* d_out, int out_size) {
    const float* c  = (const float*)d_in[0];
    const int*   gt = (const int*)d_in[1];
    const float* pr = (const float*)d_in[2];
    const float* fg = (const float*)d_in[3];
    const float* fb = (const float*)d_in[4];
    const float* mg = (const float*)d_in[5];
    const float* mb = (const float*)d_in[6];

    float* out   = (float*)d_out;
    float* o_seg = out;                                    // 4*19*128*256 = 2490368
    float* o_pl  = out + 2490368;                          // N*190 = 24903680
    float* o_pt  = out + 2490368 + 24903680;               // N
    float* o_pn  = out + 2490368 + 24903680 + N_PIX;       // 190*720

    const int SMEM_GEMM = (128 * SS_PITCH) * 4 + 128;      // 98944 B
    cudaFuncSetAttribute(k_gemm, cudaFuncAttributeMaxDynamicSharedMemorySize, SMEM_GEMM);

    k_zero<<<(NJP * DIM + 255) / 256, 256>>>();
    k_protos<<<NJP, 256>>>(pr);
    k_stats<<<N_PIX / 256, 256>>>(c, fg, fb);
    {
        dim3 g(15, N_PIX / 32);
        k_writec<<<g, 256>>>(c, fg, fb);
    }
    k_gemm<<<N_PIX / GBM, 256, SMEM_GEMM>>>(gt, mg, mb, o_seg, o_pl);
    for (int it = 0; it < 3; it++) {
        k_zeroS1<<<1, NJP>>>();
        k_sinkA<<<256, 256>>>(gt, it > 0 ? 1 : 0);
        k_sinkB<<<N_PIX / 256, 256>>>(gt, it == 2 ? 1 : 0, o_pt);
    }
    k_scatter<<<512, 256>>>(gt);
    k_update<<<NJ, 256>>>(o_pn);
}